// round 6
// baseline (speedup 1.0000x reference)
#include <cuda_runtime.h>
#include <cuda_bf16.h>
#include <stdint.h>

#define B_DIM 64
#define C_DIM 128
#define HW_DIM 16384
#define L_DIM 50
#define TILES_PER_CTA 8
#define TILE_PX 128
#define CHUNK_CH 16
#define CHUNKS_PER_TILE 8
#define NBUF 4

// shared memory map (u32 units)
#define STAG_OFF32  0                      // 4 bufs x 16ch x 128px = 8192
#define STAG_BUF32  2048
#define XIMG_OFF32  8192                   // bf16x2 image [px][colmap], stride 65
#define XIMG_STRIDE 65                     // 65*128 = 8320
#define SSQ_OFF32   16512                  // 256 floats
#define SMEM_U32    16768
#define SMEM_BYTES  (SMEM_U32 * 4)         // 67072

static __device__ __align__(16) uint2 g_kfrag2[2048];
static __device__ __align__(16) uint4 g_vfrag4[2048];

// ---------------------------------------------------------------- helpers
__device__ __forceinline__ uint32_t smem_u32(const void* p) {
    uint32_t a;
    asm("{ .reg .u64 t; cvta.to.shared.u64 t, %1; cvt.u32.u64 %0, t; }"
        : "=r"(a) : "l"(p));
    return a;
}
__device__ __forceinline__ void cp_async16(uint32_t dst, const void* src) {
    asm volatile("cp.async.cg.shared.global [%0], [%1], 16;"
                 :: "r"(dst), "l"(src));
}
__device__ __forceinline__ void cp_async_commit() {
    asm volatile("cp.async.commit_group;");
}
__device__ __forceinline__ void cp_async_wait2() {
    asm volatile("cp.async.wait_group 2;");
}
__device__ __forceinline__ uint32_t packbf(float lo, float hi) {
    __nv_bfloat162 t = __floats2bfloat162_rn(lo, hi);
    return *(uint32_t*)&t;
}
__device__ __forceinline__ void split2(float a, float b, uint32_t& hi, uint32_t& lo) {
    __nv_bfloat16 ha = __float2bfloat16(a);
    __nv_bfloat16 hb = __float2bfloat16(b);
    hi = ((uint32_t)__bfloat16_as_ushort(hb) << 16) | (uint32_t)__bfloat16_as_ushort(ha);
    lo = packbf(a - __bfloat162float(ha), b - __bfloat162float(hb));
}
__device__ __forceinline__ void mma_bf16(float* d, const uint32_t* a,
                                         const uint32_t* b, const float* c) {
    asm volatile(
        "mma.sync.aligned.m16n8k16.row.col.f32.bf16.bf16.f32 "
        "{%0,%1,%2,%3}, {%4,%5,%6,%7}, {%8,%9}, {%10,%11,%12,%13};"
        : "=f"(d[0]), "=f"(d[1]), "=f"(d[2]), "=f"(d[3])
        : "r"(a[0]), "r"(a[1]), "r"(a[2]), "r"(a[3]),
          "r"(b[0]), "r"(b[1]),
          "f"(c[0]), "f"(c[1]), "f"(c[2]), "f"(c[3]));
}

// ---------------------------------------------------------------- prep
//   kf2[(ks*8+nt)*32+lane]  = uint2{ b(r=0), b(r=1) }          (GEMM1 B, bf16)
//   vf4[(ks*16+nt)*32+lane] = uint4{ vh(r0), vh(r1), vl(r0), vl(r1) } (GEMM2 B)
__global__ void prep_kernel(const float* __restrict__ keys,
                            const float* __restrict__ values) {
    __shared__ float knorm[64];
    int tid = threadIdx.x;
    if (tid < 64) {
        float s = 0.f;
        if (tid < L_DIM) {
            for (int c = 0; c < C_DIM; c++) {
                float v = keys[tid * C_DIM + c];
                s += v * v;
            }
        }
        knorm[tid] = (tid < L_DIM) ? rsqrtf(fmaxf(s, 1e-24f)) : 0.f;
    }
    __syncthreads();

    for (int idx = tid; idx < 2048; idx += blockDim.x) {
        int lane = idx & 31, f = idx >> 5;
        int nt = f & 7, ks = f >> 3;
        int g = lane >> 2, q = lane & 3;
        int l = nt * 8 + g;
        uint2 o = make_uint2(0u, 0u);
        if (l < L_DIM) {
            float nrm = knorm[l];
            int k0 = ks * 16 + 2 * q;
            o.x = packbf(keys[l * C_DIM + k0]     * nrm,
                         keys[l * C_DIM + k0 + 1] * nrm);
            o.y = packbf(keys[l * C_DIM + k0 + 8]     * nrm,
                         keys[l * C_DIM + k0 + 8 + 1] * nrm);
        }
        g_kfrag2[idx] = o;
    }
    for (int idx = tid; idx < 2048; idx += blockDim.x) {
        int lane = idx & 31, f = idx >> 5;
        int nt = f & 15, ks = f >> 4;
        int g = lane >> 2, q = lane & 3;
        int n = nt * 8 + g;
        int k0 = ks * 16 + 2 * q;
        int k1 = k0 + 8;
        float a0 = (k0     < L_DIM) ? values[k0 * C_DIM + n]       : 0.f;
        float a1 = (k0 + 1 < L_DIM) ? values[(k0 + 1) * C_DIM + n] : 0.f;
        float b0 = (k1     < L_DIM) ? values[k1 * C_DIM + n]       : 0.f;
        float b1 = (k1 + 1 < L_DIM) ? values[(k1 + 1) * C_DIM + n] : 0.f;
        uint4 o;
        split2(a0, a1, o.x, o.z);
        split2(b0, b1, o.y, o.w);
        g_vfrag4[idx] = o;
    }
}

// ---------------------------------------------------------------- main
__global__ void __launch_bounds__(256, 2)
memmod_kernel(const float* __restrict__ x, float* __restrict__ out) {
    extern __shared__ float smem[];
    uint32_t* sm32 = (uint32_t*)smem;
    const uint32_t sbase = smem_u32(smem);

    const int tid  = threadIdx.x;
    const int wid  = tid >> 5;
    const int lane = tid & 31;
    const int g    = lane >> 2;
    const int q    = lane & 3;
    const int b    = blockIdx.y;

    const float* xb = x   + (size_t)b * C_DIM * HW_DIM;
    float*       ob = out + (size_t)b * C_DIM * HW_DIM;

    const int m0   = wid * 16;
    const int row0 = m0 + g;
    const int row1 = m0 + g + 8;
    const int p    = tid & 127;
    const int hh   = tid >> 7;

    const uint32_t* xim = sm32 + XIMG_OFF32;
    const uint2* kf2 = g_kfrag2;
    const uint4* vf4 = g_vfrag4;

    const int tile0 = blockIdx.x * TILES_PER_CTA;
    const int c_ld  = tid >> 5;
    const int j4    = (tid & 31) << 2;

    auto issue_chunk = [&](int gc) {
        if (gc < TILES_PER_CTA * CHUNKS_PER_TILE) {
            int tt = gc >> 3, cc = gc & 7;
            int nn0 = (tile0 + tt) * TILE_PX;
            uint32_t buf = sbase + (uint32_t)((gc & (NBUF - 1)) * STAG_BUF32) * 4;
            #pragma unroll
            for (int i = 0; i < 2; i++) {
                int c = c_ld + i * 8;
                cp_async16(buf + (uint32_t)(c * 128 + j4) * 4,
                           xb + (size_t)(cc * CHUNK_CH + c) * HW_DIM + nn0 + j4);
            }
        }
        cp_async_commit();
    };

    issue_chunk(0);
    issue_chunk(1);
    issue_chunk(2);

    for (int t = 0; t < TILES_PER_CTA; t++) {
        const int n0 = (tile0 + t) * TILE_PX;

        // ---- convert: 8 chunks, depth-3 in-flight, ONE sync per chunk ----
        float ssq = 0.f;
        for (int c = 0; c < CHUNKS_PER_TILE; c++) {
            const int gc = t * CHUNKS_PER_TILE + c;
            cp_async_wait2();      // chunk gc arrived (<=2 pending after)
            __syncthreads();       // visibility + all threads done with buf (gc-1)%4
            const float* buf = smem + (gc & (NBUF - 1)) * STAG_BUF32;
            #pragma unroll
            for (int jj = 0; jj < 4; jj++) {
                int ccl = hh * 4 + jj;
                int cc  = c * 8 + ccl;
                float v0 = buf[(2 * ccl)     * 128 + p];
                float v1 = buf[(2 * ccl + 1) * 128 + p];
                ssq += v0 * v0 + v1 * v1;
                int colmap = ((cc & 7) << 3) | (cc >> 3);
                sm32[XIMG_OFF32 + p * XIMG_STRIDE + colmap] = packbf(v0, v1);
            }
            // target buffer (gc+3)%4 == (gc-1)%4: finished by all threads
            // before the sync above (their convert of gc-1 preceded it).
            issue_chunk(gc + 3);
        }
        smem[SSQ_OFF32 + tid] = ssq;
        __syncthreads();

        // ---- GEMM1: logits[16px x 64slots] per warp, 1-pass bf16 ----
        float acc1[8][4];
        #pragma unroll
        for (int nt = 0; nt < 8; nt++)
            #pragma unroll
            for (int i = 0; i < 4; i++) acc1[nt][i] = 0.f;

        #pragma unroll
        for (int ks = 0; ks < 8; ks++) {
            uint32_t a[4];
            int base0 = row0 * XIMG_STRIDE + 8 * q + ks;
            int base1 = row1 * XIMG_STRIDE + 8 * q + ks;
            a[0] = xim[base0];
            a[1] = xim[base1];
            a[2] = xim[base0 + 32];
            a[3] = xim[base1 + 32];
            #pragma unroll
            for (int nt = 0; nt < 8; nt++) {
                uint2 bb = __ldg(&kf2[(ks * 8 + nt) * 32 + lane]);
                mma_bf16(acc1[nt], a, (const uint32_t*)&bb, acc1[nt]);
            }
        }

        // ---- softmax over 64 slots (quad-distributed), fp32 ----
        float rn0 = rsqrtf(fmaxf(smem[SSQ_OFF32 + row0] +
                                 smem[SSQ_OFF32 + row0 + 128], 1e-24f));
        float rn1 = rsqrtf(fmaxf(smem[SSQ_OFF32 + row1] +
                                 smem[SSQ_OFF32 + row1 + 128], 1e-24f));
        float mx0 = -1e30f, mx1 = -1e30f;
        #pragma unroll
        for (int nt = 0; nt < 8; nt++) {
            int l0 = nt * 8 + 2 * q, l1 = l0 + 1;
            acc1[nt][0] = (l0 < L_DIM) ? acc1[nt][0] * rn0 : -1e30f;
            acc1[nt][1] = (l1 < L_DIM) ? acc1[nt][1] * rn0 : -1e30f;
            acc1[nt][2] = (l0 < L_DIM) ? acc1[nt][2] * rn1 : -1e30f;
            acc1[nt][3] = (l1 < L_DIM) ? acc1[nt][3] * rn1 : -1e30f;
            mx0 = fmaxf(mx0, fmaxf(acc1[nt][0], acc1[nt][1]));
            mx1 = fmaxf(mx1, fmaxf(acc1[nt][2], acc1[nt][3]));
        }
        mx0 = fmaxf(mx0, __shfl_xor_sync(0xffffffffu, mx0, 1));
        mx0 = fmaxf(mx0, __shfl_xor_sync(0xffffffffu, mx0, 2));
        mx1 = fmaxf(mx1, __shfl_xor_sync(0xffffffffu, mx1, 1));
        mx1 = fmaxf(mx1, __shfl_xor_sync(0xffffffffu, mx1, 2));
        float s0 = 0.f, s1 = 0.f;
        #pragma unroll
        for (int nt = 0; nt < 8; nt++) {
            acc1[nt][0] = __expf(acc1[nt][0] - mx0);
            acc1[nt][1] = __expf(acc1[nt][1] - mx0);
            acc1[nt][2] = __expf(acc1[nt][2] - mx1);
            acc1[nt][3] = __expf(acc1[nt][3] - mx1);
            s0 += acc1[nt][0] + acc1[nt][1];
            s1 += acc1[nt][2] + acc1[nt][3];
        }
        s0 += __shfl_xor_sync(0xffffffffu, s0, 1);
        s0 += __shfl_xor_sync(0xffffffffu, s0, 2);
        s1 += __shfl_xor_sync(0xffffffffu, s1, 1);
        s1 += __shfl_xor_sync(0xffffffffu, s1, 2);
        float inv0 = 1.f / s0, inv1 = 1.f / s1;

        // weights -> GEMM2 A-frags (hi/lo), direct D->A layout mapping
        uint32_t wh[4][4], wl[4][4];
        #pragma unroll
        for (int ks = 0; ks < 4; ks++) {
            int ntA = 2 * ks, ntB = 2 * ks + 1;
            split2(acc1[ntA][0] * inv0, acc1[ntA][1] * inv0, wh[ks][0], wl[ks][0]);
            split2(acc1[ntA][2] * inv1, acc1[ntA][3] * inv1, wh[ks][1], wl[ks][1]);
            split2(acc1[ntB][0] * inv0, acc1[ntB][1] * inv0, wh[ks][2], wl[ks][2]);
            split2(acc1[ntB][2] * inv1, acc1[ntB][3] * inv1, wh[ks][3], wl[ks][3]);
        }

        // ---- GEMM2 in two halves of 8 n-tiles ----
        #pragma unroll
        for (int half = 0; half < 2; half++) {
            float acc2[8][4];
            #pragma unroll
            for (int nt = 0; nt < 8; nt++)
                #pragma unroll
                for (int i = 0; i < 4; i++) acc2[nt][i] = 0.f;

            #pragma unroll
            for (int nt = 0; nt < 8; nt++) {
                int ntg = half * 8 + nt;
                #pragma unroll
                for (int ks = 0; ks < 4; ks++) {
                    uint4 v = __ldg(&vf4[(ks * 16 + ntg) * 32 + lane]);
                    uint32_t bhv[2] = { v.x, v.y };
                    uint32_t blv[2] = { v.z, v.w };
                    mma_bf16(acc2[nt], wh[ks], bhv, acc2[nt]);
                    mma_bf16(acc2[nt], wl[ks], bhv, acc2[nt]);
                    mma_bf16(acc2[nt], wh[ks], blv, acc2[nt]);
                }
            }
            #pragma unroll
            for (int nt = 0; nt < 8; nt++) {
                int c0 = (half * 8 + nt) * 8 + 2 * q;
                size_t base = (size_t)c0 * HW_DIM + n0;
                __stcs(&ob[base + row0],          acc2[nt][0]);
                __stcs(&ob[base + HW_DIM + row0], acc2[nt][1]);
                __stcs(&ob[base + row1],          acc2[nt][2]);
                __stcs(&ob[base + HW_DIM + row1], acc2[nt][3]);
            }
        }
    }
}

// ---------------------------------------------------------------- launcher
extern "C" void kernel_launch(void* const* d_in, const int* in_sizes, int n_in,
                              void* d_out, int out_size) {
    const float* x      = (const float*)d_in[0];
    const float* keys   = (const float*)d_in[1];
    const float* values = (const float*)d_in[2];
    float* out = (float*)d_out;

    cudaFuncSetAttribute(memmod_kernel,
                         cudaFuncAttributeMaxDynamicSharedMemorySize, SMEM_BYTES);

    prep_kernel<<<1, 256>>>(keys, values);
    dim3 grid(HW_DIM / (TILES_PER_CTA * TILE_PX), B_DIM);
    memmod_kernel<<<grid, 256, SMEM_BYTES>>>(x, out);
}

// round 7
// speedup vs baseline: 1.0581x; 1.0581x over previous
#include <cuda_runtime.h>
#include <cuda_bf16.h>
#include <stdint.h>

#define B_DIM 64
#define C_DIM 128
#define HW_DIM 16384
#define L_DIM 50
#define TILES_PER_CTA 8
#define TILE_PX 128
#define CHUNK_CH 16
#define CHUNKS_PER_TILE 8
#define NBUF 4

// shared memory map (u32 units)
#define STAG_OFF32  0                      // 4 bufs x 16ch x 128px = 8192
#define STAG_BUF32  2048
#define XIMG_OFF32  8192                   // bf16x2 image [px][colmap], stride 65
#define XIMG_STRIDE 65                     // end 16512
#define SSQ_OFF32   16512                  // 256 floats -> end 16768
#define KF_OFF32    16768                  // 1792 uint2 = 3584 u32 -> end 20352
#define VF4_OFF32   20352                  // 1536 uint4 = 6144 u32 -> end 26496
#define VF3_OFF32   26496                  // 512 uint2 = 1024 u32 -> end 27520
#define SMEM_U32    27520
#define SMEM_BYTES  (SMEM_U32 * 4)         // 110080

static __device__ __align__(16) uint2 g_kfrag2[1792];   // 7 nt x 8 ks x 32
static __device__ __align__(16) uint4 g_vfrag4[1536];   // 3 ks x 16 nt x 32
static __device__ __align__(16) uint2 g_vfrag3[512];    // 16 nt x 32 (ks=3, r0)

// ---------------------------------------------------------------- helpers
__device__ __forceinline__ uint32_t smem_u32(const void* p) {
    uint32_t a;
    asm("{ .reg .u64 t; cvta.to.shared.u64 t, %1; cvt.u32.u64 %0, t; }"
        : "=r"(a) : "l"(p));
    return a;
}
__device__ __forceinline__ void cp_async16(uint32_t dst, const void* src) {
    asm volatile("cp.async.cg.shared.global [%0], [%1], 16;"
                 :: "r"(dst), "l"(src));
}
__device__ __forceinline__ void cp_async_commit() {
    asm volatile("cp.async.commit_group;");
}
__device__ __forceinline__ void cp_async_wait2() {
    asm volatile("cp.async.wait_group 2;");
}
__device__ __forceinline__ uint32_t packbf(float lo, float hi) {
    __nv_bfloat162 t = __floats2bfloat162_rn(lo, hi);
    return *(uint32_t*)&t;
}
__device__ __forceinline__ void split2(float a, float b, uint32_t& hi, uint32_t& lo) {
    __nv_bfloat16 ha = __float2bfloat16(a);
    __nv_bfloat16 hb = __float2bfloat16(b);
    hi = ((uint32_t)__bfloat16_as_ushort(hb) << 16) | (uint32_t)__bfloat16_as_ushort(ha);
    lo = packbf(a - __bfloat162float(ha), b - __bfloat162float(hb));
}
__device__ __forceinline__ void mma_bf16(float* d, const uint32_t* a,
                                         const uint32_t* b, const float* c) {
    asm volatile(
        "mma.sync.aligned.m16n8k16.row.col.f32.bf16.bf16.f32 "
        "{%0,%1,%2,%3}, {%4,%5,%6,%7}, {%8,%9}, {%10,%11,%12,%13};"
        : "=f"(d[0]), "=f"(d[1]), "=f"(d[2]), "=f"(d[3])
        : "r"(a[0]), "r"(a[1]), "r"(a[2]), "r"(a[3]),
          "r"(b[0]), "r"(b[1]),
          "f"(c[0]), "f"(c[1]), "f"(c[2]), "f"(c[3]));
}
__device__ __forceinline__ void mma_bf16_k8(float* d, uint32_t a0, uint32_t a1,
                                            uint32_t b0, const float* c) {
    asm volatile(
        "mma.sync.aligned.m16n8k8.row.col.f32.bf16.bf16.f32 "
        "{%0,%1,%2,%3}, {%4,%5}, {%6}, {%7,%8,%9,%10};"
        : "=f"(d[0]), "=f"(d[1]), "=f"(d[2]), "=f"(d[3])
        : "r"(a0), "r"(a1), "r"(b0),
          "f"(c[0]), "f"(c[1]), "f"(c[2]), "f"(c[3]));
}

// ---------------------------------------------------------------- prep
//   kf2[(ks*7+nt)*32+lane]  = uint2{ b(r=0), b(r=1) }       GEMM1 B, nt<7
//   vf4[(ks*16+nt)*32+lane] = uint4{ vh0, vh1, vl0, vl1 }   GEMM2 B, ks<3
//   vf3[nt*32+lane]         = uint2{ vh(r0), vl(r0) }       GEMM2 B, ks=3 k8
__global__ void prep_kernel(const float* __restrict__ keys,
                            const float* __restrict__ values) {
    __shared__ float knorm[64];
    int tid = threadIdx.x;
    if (tid < 64) {
        float s = 0.f;
        if (tid < L_DIM) {
            for (int c = 0; c < C_DIM; c++) {
                float v = keys[tid * C_DIM + c];
                s += v * v;
            }
        }
        knorm[tid] = (tid < L_DIM) ? rsqrtf(fmaxf(s, 1e-24f)) : 0.f;
    }
    __syncthreads();

    for (int idx = tid; idx < 1792; idx += blockDim.x) {
        int lane = idx & 31, f = idx >> 5;
        int nt = f % 7, ks = f / 7;
        int g = lane >> 2, q = lane & 3;
        int l = nt * 8 + g;
        uint2 o = make_uint2(0u, 0u);
        if (l < L_DIM) {
            float nrm = knorm[l];
            int k0 = ks * 16 + 2 * q;
            o.x = packbf(keys[l * C_DIM + k0]     * nrm,
                         keys[l * C_DIM + k0 + 1] * nrm);
            o.y = packbf(keys[l * C_DIM + k0 + 8]     * nrm,
                         keys[l * C_DIM + k0 + 8 + 1] * nrm);
        }
        g_kfrag2[idx] = o;
    }
    for (int idx = tid; idx < 1536; idx += blockDim.x) {
        int lane = idx & 31, f = idx >> 5;
        int nt = f & 15, ks = f >> 4;            // ks < 3 -> slots < 48 real
        int g = lane >> 2, q = lane & 3;
        int n = nt * 8 + g;
        int k0 = ks * 16 + 2 * q;
        int k1 = k0 + 8;
        float a0 = values[k0 * C_DIM + n];
        float a1 = values[(k0 + 1) * C_DIM + n];
        float b0 = values[k1 * C_DIM + n];
        float b1 = values[(k1 + 1) * C_DIM + n];
        uint4 o;
        split2(a0, a1, o.x, o.z);
        split2(b0, b1, o.y, o.w);
        g_vfrag4[idx] = o;
    }
    for (int idx = tid; idx < 512; idx += blockDim.x) {
        int lane = idx & 31, nt = idx >> 5;
        int g = lane >> 2, q = lane & 3;
        int n = nt * 8 + g;
        int k0 = 48 + 2 * q;                     // slots 48..55 (r0 of ks=3)
        float a0 = (k0     < L_DIM) ? values[k0 * C_DIM + n]       : 0.f;
        float a1 = (k0 + 1 < L_DIM) ? values[(k0 + 1) * C_DIM + n] : 0.f;
        uint2 o;
        split2(a0, a1, o.x, o.y);
        g_vfrag3[idx] = o;
    }
}

// ---------------------------------------------------------------- main
__global__ void __launch_bounds__(256, 2)
memmod_kernel(const float* __restrict__ x, float* __restrict__ out) {
    extern __shared__ float smem[];
    uint32_t* sm32 = (uint32_t*)smem;
    const uint32_t sbase = smem_u32(smem);

    const int tid  = threadIdx.x;
    const int wid  = tid >> 5;
    const int lane = tid & 31;
    const int g    = lane >> 2;
    const int q    = lane & 3;
    const int b    = blockIdx.y;

    // copy baked fragment images into smem (~42 KB)
    {
        const uint4* s1 = (const uint4*)g_kfrag2;   // 896 uint4
        const uint4* s2 = (const uint4*)g_vfrag4;   // 1536 uint4
        const uint4* s3 = (const uint4*)g_vfrag3;   // 256 uint4
        uint4* d1 = (uint4*)(sm32 + KF_OFF32);
        uint4* d2 = (uint4*)(sm32 + VF4_OFF32);
        uint4* d3 = (uint4*)(sm32 + VF3_OFF32);
        for (int i = tid; i < 896;  i += 256) d1[i] = s1[i];
        for (int i = tid; i < 1536; i += 256) d2[i] = s2[i];
        if (tid < 256) d3[tid] = s3[tid];
    }
    __syncthreads();

    const float* xb = x   + (size_t)b * C_DIM * HW_DIM;
    float*       ob = out + (size_t)b * C_DIM * HW_DIM;

    const int m0   = wid * 16;
    const int row0 = m0 + g;
    const int row1 = m0 + g + 8;
    const int p    = tid & 127;
    const int hh   = tid >> 7;

    const uint32_t* xim = sm32 + XIMG_OFF32;
    const uint2* kf2 = (const uint2*)(sm32 + KF_OFF32);
    const uint4* vf4 = (const uint4*)(sm32 + VF4_OFF32);
    const uint2* vf3 = (const uint2*)(sm32 + VF3_OFF32);

    const int tile0 = blockIdx.x * TILES_PER_CTA;
    const int c_ld  = tid >> 5;
    const int j4    = (tid & 31) << 2;

    auto issue_chunk = [&](int gc) {
        if (gc < TILES_PER_CTA * CHUNKS_PER_TILE) {
            int tt = gc >> 3, cc = gc & 7;
            int nn0 = (tile0 + tt) * TILE_PX;
            uint32_t buf = sbase + (uint32_t)((gc & (NBUF - 1)) * STAG_BUF32) * 4;
            #pragma unroll
            for (int i = 0; i < 2; i++) {
                int c = c_ld + i * 8;
                cp_async16(buf + (uint32_t)(c * 128 + j4) * 4,
                           xb + (size_t)(cc * CHUNK_CH + c) * HW_DIM + nn0 + j4);
            }
        }
        cp_async_commit();
    };

    issue_chunk(0);
    issue_chunk(1);
    issue_chunk(2);

    for (int t = 0; t < TILES_PER_CTA; t++) {
        const int n0 = (tile0 + t) * TILE_PX;

        // ---- convert: 8 chunks of 16 ch, depth-3 in flight, 1 sync/chunk ----
        float ssq = 0.f;
        for (int c = 0; c < CHUNKS_PER_TILE; c++) {
            const int gc = t * CHUNKS_PER_TILE + c;
            cp_async_wait2();
            __syncthreads();
            const float* buf = smem + (gc & (NBUF - 1)) * STAG_BUF32;
            #pragma unroll
            for (int jj = 0; jj < 4; jj++) {
                int ccl = hh * 4 + jj;
                int cc  = c * 8 + ccl;
                float v0 = buf[(2 * ccl)     * 128 + p];
                float v1 = buf[(2 * ccl + 1) * 128 + p];
                ssq += v0 * v0 + v1 * v1;
                int colmap = ((cc & 7) << 3) | (cc >> 3);
                sm32[XIMG_OFF32 + p * XIMG_STRIDE + colmap] = packbf(v0, v1);
            }
            issue_chunk(gc + 3);   // targets buf (gc-1)&3: all done pre-sync
        }
        smem[SSQ_OFF32 + tid] = ssq;
        __syncthreads();

        // ---- GEMM1: logits[16px x 56slots] per warp (nt7 = pure padding) ----
        float acc1[7][4];
        #pragma unroll
        for (int nt = 0; nt < 7; nt++)
            #pragma unroll
            for (int i = 0; i < 4; i++) acc1[nt][i] = 0.f;

        #pragma unroll
        for (int ks = 0; ks < 8; ks++) {
            uint32_t a[4];
            int base0 = row0 * XIMG_STRIDE + 8 * q + ks;
            int base1 = row1 * XIMG_STRIDE + 8 * q + ks;
            a[0] = xim[base0];
            a[1] = xim[base1];
            a[2] = xim[base0 + 32];
            a[3] = xim[base1 + 32];
            #pragma unroll
            for (int nt = 0; nt < 7; nt++) {
                uint2 bb = kf2[(ks * 7 + nt) * 32 + lane];
                mma_bf16(acc1[nt], a, (const uint32_t*)&bb, acc1[nt]);
            }
        }

        // ---- softmax over 56 slots (quad-distributed), fp32 ----
        float rn0 = rsqrtf(fmaxf(smem[SSQ_OFF32 + row0] +
                                 smem[SSQ_OFF32 + row0 + 128], 1e-24f));
        float rn1 = rsqrtf(fmaxf(smem[SSQ_OFF32 + row1] +
                                 smem[SSQ_OFF32 + row1 + 128], 1e-24f));
        float mx0 = -1e30f, mx1 = -1e30f;
        #pragma unroll
        for (int nt = 0; nt < 7; nt++) {
            int l0 = nt * 8 + 2 * q, l1 = l0 + 1;
            acc1[nt][0] = (l0 < L_DIM) ? acc1[nt][0] * rn0 : -1e30f;
            acc1[nt][1] = (l1 < L_DIM) ? acc1[nt][1] * rn0 : -1e30f;
            acc1[nt][2] = (l0 < L_DIM) ? acc1[nt][2] * rn1 : -1e30f;
            acc1[nt][3] = (l1 < L_DIM) ? acc1[nt][3] * rn1 : -1e30f;
            mx0 = fmaxf(mx0, fmaxf(acc1[nt][0], acc1[nt][1]));
            mx1 = fmaxf(mx1, fmaxf(acc1[nt][2], acc1[nt][3]));
        }
        mx0 = fmaxf(mx0, __shfl_xor_sync(0xffffffffu, mx0, 1));
        mx0 = fmaxf(mx0, __shfl_xor_sync(0xffffffffu, mx0, 2));
        mx1 = fmaxf(mx1, __shfl_xor_sync(0xffffffffu, mx1, 1));
        mx1 = fmaxf(mx1, __shfl_xor_sync(0xffffffffu, mx1, 2));
        float s0 = 0.f, s1 = 0.f;
        #pragma unroll
        for (int nt = 0; nt < 7; nt++) {
            acc1[nt][0] = __expf(acc1[nt][0] - mx0);
            acc1[nt][1] = __expf(acc1[nt][1] - mx0);
            acc1[nt][2] = __expf(acc1[nt][2] - mx1);
            acc1[nt][3] = __expf(acc1[nt][3] - mx1);
            s0 += acc1[nt][0] + acc1[nt][1];
            s1 += acc1[nt][2] + acc1[nt][3];
        }
        s0 += __shfl_xor_sync(0xffffffffu, s0, 1);
        s0 += __shfl_xor_sync(0xffffffffu, s0, 2);
        s1 += __shfl_xor_sync(0xffffffffu, s1, 1);
        s1 += __shfl_xor_sync(0xffffffffu, s1, 2);
        float inv0 = 1.f / s0, inv1 = 1.f / s1;

        // weights -> GEMM2 A-frags; ks<3 full k16, ks=3 only r0 (k8)
        uint32_t wh[3][4], wl[3][4];
        #pragma unroll
        for (int ks = 0; ks < 3; ks++) {
            int ntA = 2 * ks, ntB = 2 * ks + 1;
            split2(acc1[ntA][0] * inv0, acc1[ntA][1] * inv0, wh[ks][0], wl[ks][0]);
            split2(acc1[ntA][2] * inv1, acc1[ntA][3] * inv1, wh[ks][1], wl[ks][1]);
            split2(acc1[ntB][0] * inv0, acc1[ntB][1] * inv0, wh[ks][2], wl[ks][2]);
            split2(acc1[ntB][2] * inv1, acc1[ntB][3] * inv1, wh[ks][3], wl[ks][3]);
        }
        uint32_t wh3[2], wl3[2];
        split2(acc1[6][0] * inv0, acc1[6][1] * inv0, wh3[0], wl3[0]);
        split2(acc1[6][2] * inv1, acc1[6][3] * inv1, wh3[1], wl3[1]);

        // ---- GEMM2 in two halves of 8 n-tiles ----
        #pragma unroll
        for (int half = 0; half < 2; half++) {
            float acc2[8][4];
            #pragma unroll
            for (int nt = 0; nt < 8; nt++)
                #pragma unroll
                for (int i = 0; i < 4; i++) acc2[nt][i] = 0.f;

            #pragma unroll
            for (int nt = 0; nt < 8; nt++) {
                int ntg = half * 8 + nt;
                #pragma unroll
                for (int ks = 0; ks < 3; ks++) {
                    uint4 v = vf4[(ks * 16 + ntg) * 32 + lane];
                    uint32_t bhv[2] = { v.x, v.y };
                    uint32_t blv[2] = { v.z, v.w };
                    mma_bf16(acc2[nt], wh[ks], bhv, acc2[nt]);
                    mma_bf16(acc2[nt], wl[ks], bhv, acc2[nt]);
                    mma_bf16(acc2[nt], wh[ks], blv, acc2[nt]);
                }
                uint2 v3 = vf3[ntg * 32 + lane];
                mma_bf16_k8(acc2[nt], wh3[0], wh3[1], v3.x, acc2[nt]);
                mma_bf16_k8(acc2[nt], wl3[0], wl3[1], v3.x, acc2[nt]);
                mma_bf16_k8(acc2[nt], wh3[0], wh3[1], v3.y, acc2[nt]);
            }
            #pragma unroll
            for (int nt = 0; nt < 8; nt++) {
                int c0 = (half * 8 + nt) * 8 + 2 * q;
                size_t base = (size_t)c0 * HW_DIM + n0;
                __stcs(&ob[base + row0],          acc2[nt][0]);
                __stcs(&ob[base + HW_DIM + row0], acc2[nt][1]);
                __stcs(&ob[base + row1],          acc2[nt][2]);
                __stcs(&ob[base + HW_DIM + row1], acc2[nt][3]);
            }
        }
    }
}

// ---------------------------------------------------------------- launcher
extern "C" void kernel_launch(void* const* d_in, const int* in_sizes, int n_in,
                              void* d_out, int out_size) {
    const float* x      = (const float*)d_in[0];
    const float* keys   = (const float*)d_in[1];
    const float* values = (const float*)d_in[2];
    float* out = (float*)d_out;

    cudaFuncSetAttribute(memmod_kernel,
                         cudaFuncAttributeMaxDynamicSharedMemorySize, SMEM_BYTES);

    prep_kernel<<<1, 256>>>(keys, values);
    dim3 grid(HW_DIM / (TILES_PER_CTA * TILE_PX), B_DIM);
    memmod_kernel<<<grid, 256, SMEM_BYTES>>>(x, out);
}

// round 8
// speedup vs baseline: 1.2057x; 1.1395x over previous
#include <cuda_runtime.h>
#include <cuda_bf16.h>
#include <stdint.h>

#define B_DIM 64
#define C_DIM 128
#define HW_DIM 16384
#define L_DIM 50
#define TILES_PER_CTA 8
#define TILE_PX 128

// shared memory: fragment images only (u32 units)
#define KF_OFF32  0                        // 1792 uint2 = 3584 u32
#define VF4_OFF32 3584                     // 1536 uint4 = 6144 u32
#define VF3_OFF32 9728                     // 512 uint2  = 1024 u32
#define SMEM_U32  10752
#define SMEM_BYTES (SMEM_U32 * 4)          // 43008

static __device__ __align__(16) uint2 g_kfrag2[1792];   // 8 ks x 7 nt x 32
static __device__ __align__(16) uint4 g_vfrag4[1536];   // 3 ks x 16 nt x 32
static __device__ __align__(16) uint2 g_vfrag3[512];    // 16 nt x 32 (ks=3 r0)

// ---------------------------------------------------------------- helpers
__device__ __forceinline__ uint32_t packbf(float lo, float hi) {
    __nv_bfloat162 t = __floats2bfloat162_rn(lo, hi);
    return *(uint32_t*)&t;
}
__device__ __forceinline__ void split2(float a, float b, uint32_t& hi, uint32_t& lo) {
    __nv_bfloat16 ha = __float2bfloat16(a);
    __nv_bfloat16 hb = __float2bfloat16(b);
    hi = ((uint32_t)__bfloat16_as_ushort(hb) << 16) | (uint32_t)__bfloat16_as_ushort(ha);
    lo = packbf(a - __bfloat162float(ha), b - __bfloat162float(hb));
}
__device__ __forceinline__ void mma_bf16(float* d, const uint32_t* a,
                                         const uint32_t* b, const float* c) {
    asm volatile(
        "mma.sync.aligned.m16n8k16.row.col.f32.bf16.bf16.f32 "
        "{%0,%1,%2,%3}, {%4,%5,%6,%7}, {%8,%9}, {%10,%11,%12,%13};"
        : "=f"(d[0]), "=f"(d[1]), "=f"(d[2]), "=f"(d[3])
        : "r"(a[0]), "r"(a[1]), "r"(a[2]), "r"(a[3]),
          "r"(b[0]), "r"(b[1]),
          "f"(c[0]), "f"(c[1]), "f"(c[2]), "f"(c[3]));
}
__device__ __forceinline__ void mma_bf16_k8(float* d, uint32_t a0, uint32_t a1,
                                            uint32_t b0, const float* c) {
    asm volatile(
        "mma.sync.aligned.m16n8k8.row.col.f32.bf16.bf16.f32 "
        "{%0,%1,%2,%3}, {%4,%5}, {%6}, {%7,%8,%9,%10};"
        : "=f"(d[0]), "=f"(d[1]), "=f"(d[2]), "=f"(d[3])
        : "r"(a0), "r"(a1), "r"(b0),
          "f"(c[0]), "f"(c[1]), "f"(c[2]), "f"(c[3]));
}

// ---------------------------------------------------- prep (same as round 7)
__global__ void prep_kernel(const float* __restrict__ keys,
                            const float* __restrict__ values) {
    __shared__ float knorm[64];
    int tid = threadIdx.x;
    if (tid < 64) {
        float s = 0.f;
        if (tid < L_DIM) {
            for (int c = 0; c < C_DIM; c++) {
                float v = keys[tid * C_DIM + c];
                s += v * v;
            }
        }
        knorm[tid] = (tid < L_DIM) ? rsqrtf(fmaxf(s, 1e-24f)) : 0.f;
    }
    __syncthreads();

    for (int idx = tid; idx < 1792; idx += blockDim.x) {
        int lane = idx & 31, f = idx >> 5;
        int nt = f % 7, ks = f / 7;
        int g = lane >> 2, q = lane & 3;
        int l = nt * 8 + g;
        uint2 o = make_uint2(0u, 0u);
        if (l < L_DIM) {
            float nrm = knorm[l];
            int k0 = ks * 16 + 2 * q;
            o.x = packbf(keys[l * C_DIM + k0]     * nrm,
                         keys[l * C_DIM + k0 + 1] * nrm);
            o.y = packbf(keys[l * C_DIM + k0 + 8]     * nrm,
                         keys[l * C_DIM + k0 + 8 + 1] * nrm);
        }
        g_kfrag2[idx] = o;
    }
    for (int idx = tid; idx < 1536; idx += blockDim.x) {
        int lane = idx & 31, f = idx >> 5;
        int nt = f & 15, ks = f >> 4;
        int g = lane >> 2, q = lane & 3;
        int n = nt * 8 + g;
        int k0 = ks * 16 + 2 * q;
        int k1 = k0 + 8;
        float a0 = values[k0 * C_DIM + n];
        float a1 = values[(k0 + 1) * C_DIM + n];
        float b0 = values[k1 * C_DIM + n];
        float b1 = values[(k1 + 1) * C_DIM + n];
        uint4 o;
        split2(a0, a1, o.x, o.z);
        split2(b0, b1, o.y, o.w);
        g_vfrag4[idx] = o;
    }
    for (int idx = tid; idx < 512; idx += blockDim.x) {
        int lane = idx & 31, nt = idx >> 5;
        int g = lane >> 2, q = lane & 3;
        int n = nt * 8 + g;
        int k0 = 48 + 2 * q;
        float a0 = (k0     < L_DIM) ? values[k0 * C_DIM + n]       : 0.f;
        float a1 = (k0 + 1 < L_DIM) ? values[(k0 + 1) * C_DIM + n] : 0.f;
        uint2 o;
        split2(a0, a1, o.x, o.y);
        g_vfrag3[idx] = o;
    }
}

// ---------------------------------------------------------------- main
__global__ void __launch_bounds__(256, 2)
memmod_kernel(const float* __restrict__ x, float* __restrict__ out) {
    extern __shared__ float smem[];
    uint32_t* sm32 = (uint32_t*)smem;

    const int tid  = threadIdx.x;
    const int wid  = tid >> 5;
    const int lane = tid & 31;
    const int g    = lane >> 2;
    const int q    = lane & 3;
    const int b    = blockIdx.y;

    // copy baked fragment images into smem (42 KB, once)
    {
        const uint4* s1 = (const uint4*)g_kfrag2;   // 896 uint4
        const uint4* s2 = (const uint4*)g_vfrag4;   // 1536 uint4
        const uint4* s3 = (const uint4*)g_vfrag3;   // 256 uint4
        uint4* d1 = (uint4*)(sm32 + KF_OFF32);
        uint4* d2 = (uint4*)(sm32 + VF4_OFF32);
        uint4* d3 = (uint4*)(sm32 + VF3_OFF32);
        for (int i = tid; i < 896;  i += 256) d1[i] = s1[i];
        for (int i = tid; i < 1536; i += 256) d2[i] = s2[i];
        if (tid < 256) d3[tid] = s3[tid];
    }
    __syncthreads();   // only barrier in the kernel

    const float* xb = x   + (size_t)b * C_DIM * HW_DIM;
    float*       ob = out + (size_t)b * C_DIM * HW_DIM;

    const int m0   = wid * 16;
    const int row0 = m0 + g;
    const int row1 = m0 + g + 8;

    const uint2* kf2 = (const uint2*)(sm32 + KF_OFF32);
    const uint4* vf4 = (const uint4*)(sm32 + VF4_OFF32);
    const uint2* vf3 = (const uint2*)(sm32 + VF3_OFF32);

    const int tile0 = blockIdx.x * TILES_PER_CTA;

    for (int t = 0; t < TILES_PER_CTA; t++) {
        const int n0 = (tile0 + t) * TILE_PX;

        // ---- A-fragments straight from gmem (coalesced LDG.32, 4 sectors ea)
        // lane(g,q), ks: channels c0=16ks+2q (+1, +8, +9), rows row0/row1
        const float* xp0 = xb + n0 + row0;   // + c*HW_DIM
        const float* xp1 = xb + n0 + row1;
        float xv[8][8];
        #pragma unroll
        for (int ks = 0; ks < 8; ks++) {
            const size_t c0 = (size_t)(16 * ks + 2 * q) * HW_DIM;
            xv[ks][0] = xp0[c0];
            xv[ks][1] = xp0[c0 + HW_DIM];
            xv[ks][2] = xp1[c0];
            xv[ks][3] = xp1[c0 + HW_DIM];
            xv[ks][4] = xp0[c0 + 8 * HW_DIM];
            xv[ks][5] = xp0[c0 + 9 * HW_DIM];
            xv[ks][6] = xp1[c0 + 8 * HW_DIM];
            xv[ks][7] = xp1[c0 + 9 * HW_DIM];
        }
        float ssq0 = 0.f, ssq1 = 0.f;
        uint32_t axf[8][4];
        #pragma unroll
        for (int ks = 0; ks < 8; ks++) {
            ssq0 += xv[ks][0] * xv[ks][0] + xv[ks][1] * xv[ks][1]
                  + xv[ks][4] * xv[ks][4] + xv[ks][5] * xv[ks][5];
            ssq1 += xv[ks][2] * xv[ks][2] + xv[ks][3] * xv[ks][3]
                  + xv[ks][6] * xv[ks][6] + xv[ks][7] * xv[ks][7];
            axf[ks][0] = packbf(xv[ks][0], xv[ks][1]);
            axf[ks][1] = packbf(xv[ks][2], xv[ks][3]);
            axf[ks][2] = packbf(xv[ks][4], xv[ks][5]);
            axf[ks][3] = packbf(xv[ks][6], xv[ks][7]);
        }
        // quad reduce over q (lanes xor 1, 2 share the same row)
        ssq0 += __shfl_xor_sync(0xffffffffu, ssq0, 1);
        ssq0 += __shfl_xor_sync(0xffffffffu, ssq0, 2);
        ssq1 += __shfl_xor_sync(0xffffffffu, ssq1, 1);
        ssq1 += __shfl_xor_sync(0xffffffffu, ssq1, 2);
        float rn0 = rsqrtf(fmaxf(ssq0, 1e-24f));
        float rn1 = rsqrtf(fmaxf(ssq1, 1e-24f));

        // ---- GEMM1: logits[16px x 56slots] (nt7 = pure padding) ----
        float acc1[7][4];
        #pragma unroll
        for (int nt = 0; nt < 7; nt++)
            #pragma unroll
            for (int i = 0; i < 4; i++) acc1[nt][i] = 0.f;

        #pragma unroll
        for (int ks = 0; ks < 8; ks++) {
            #pragma unroll
            for (int nt = 0; nt < 7; nt++) {
                uint2 bb = kf2[(ks * 7 + nt) * 32 + lane];
                mma_bf16(acc1[nt], axf[ks], (const uint32_t*)&bb, acc1[nt]);
            }
        }

        // ---- softmax over 56 slots (quad-distributed), fp32 ----
        float mx0 = -1e30f, mx1 = -1e30f;
        #pragma unroll
        for (int nt = 0; nt < 7; nt++) {
            int l0 = nt * 8 + 2 * q, l1 = l0 + 1;
            acc1[nt][0] = (l0 < L_DIM) ? acc1[nt][0] * rn0 : -1e30f;
            acc1[nt][1] = (l1 < L_DIM) ? acc1[nt][1] * rn0 : -1e30f;
            acc1[nt][2] = (l0 < L_DIM) ? acc1[nt][2] * rn1 : -1e30f;
            acc1[nt][3] = (l1 < L_DIM) ? acc1[nt][3] * rn1 : -1e30f;
            mx0 = fmaxf(mx0, fmaxf(acc1[nt][0], acc1[nt][1]));
            mx1 = fmaxf(mx1, fmaxf(acc1[nt][2], acc1[nt][3]));
        }
        mx0 = fmaxf(mx0, __shfl_xor_sync(0xffffffffu, mx0, 1));
        mx0 = fmaxf(mx0, __shfl_xor_sync(0xffffffffu, mx0, 2));
        mx1 = fmaxf(mx1, __shfl_xor_sync(0xffffffffu, mx1, 1));
        mx1 = fmaxf(mx1, __shfl_xor_sync(0xffffffffu, mx1, 2));
        float s0 = 0.f, s1 = 0.f;
        #pragma unroll
        for (int nt = 0; nt < 7; nt++) {
            acc1[nt][0] = __expf(acc1[nt][0] - mx0);
            acc1[nt][1] = __expf(acc1[nt][1] - mx0);
            acc1[nt][2] = __expf(acc1[nt][2] - mx1);
            acc1[nt][3] = __expf(acc1[nt][3] - mx1);
            s0 += acc1[nt][0] + acc1[nt][1];
            s1 += acc1[nt][2] + acc1[nt][3];
        }
        s0 += __shfl_xor_sync(0xffffffffu, s0, 1);
        s0 += __shfl_xor_sync(0xffffffffu, s0, 2);
        s1 += __shfl_xor_sync(0xffffffffu, s1, 1);
        s1 += __shfl_xor_sync(0xffffffffu, s1, 2);
        float inv0 = 1.f / s0, inv1 = 1.f / s1;

        // weights -> GEMM2 A-frags; ks<3 full k16, ks=3 only r0 (k8)
        uint32_t wh[3][4], wl[3][4];
        #pragma unroll
        for (int ks = 0; ks < 3; ks++) {
            int ntA = 2 * ks, ntB = 2 * ks + 1;
            split2(acc1[ntA][0] * inv0, acc1[ntA][1] * inv0, wh[ks][0], wl[ks][0]);
            split2(acc1[ntA][2] * inv1, acc1[ntA][3] * inv1, wh[ks][1], wl[ks][1]);
            split2(acc1[ntB][0] * inv0, acc1[ntB][1] * inv0, wh[ks][2], wl[ks][2]);
            split2(acc1[ntB][2] * inv1, acc1[ntB][3] * inv1, wh[ks][3], wl[ks][3]);
        }
        uint32_t wh3[2], wl3[2];
        split2(acc1[6][0] * inv0, acc1[6][1] * inv0, wh3[0], wl3[0]);
        split2(acc1[6][2] * inv1, acc1[6][3] * inv1, wh3[1], wl3[1]);

        // ---- GEMM2 in two halves of 8 n-tiles ----
        #pragma unroll
        for (int half = 0; half < 2; half++) {
            float acc2[8][4];
            #pragma unroll
            for (int nt = 0; nt < 8; nt++)
                #pragma unroll
                for (int i = 0; i < 4; i++) acc2[nt][i] = 0.f;

            #pragma unroll
            for (int nt = 0; nt < 8; nt++) {
                int ntg = half * 8 + nt;
                #pragma unroll
                for (int ks = 0; ks < 3; ks++) {
                    uint4 v = vf4[(ks * 16 + ntg) * 32 + lane];
                    uint32_t bhv[2] = { v.x, v.y };
                    uint32_t blv[2] = { v.z, v.w };
                    mma_bf16(acc2[nt], wh[ks], bhv, acc2[nt]);
                    mma_bf16(acc2[nt], wl[ks], bhv, acc2[nt]);
                    mma_bf16(acc2[nt], wh[ks], blv, acc2[nt]);
                }
                uint2 v3 = vf3[ntg * 32 + lane];
                mma_bf16_k8(acc2[nt], wh3[0], wh3[1], v3.x, acc2[nt]);
                mma_bf16_k8(acc2[nt], wl3[0], wl3[1], v3.x, acc2[nt]);
                mma_bf16_k8(acc2[nt], wh3[0], wh3[1], v3.y, acc2[nt]);
            }
            #pragma unroll
            for (int nt = 0; nt < 8; nt++) {
                int c0 = (half * 8 + nt) * 8 + 2 * q;
                size_t base = (size_t)c0 * HW_DIM + n0;
                __stcs(&ob[base + row0],          acc2[nt][0]);
                __stcs(&ob[base + HW_DIM + row0], acc2[nt][1]);
                __stcs(&ob[base + row1],          acc2[nt][2]);
                __stcs(&ob[base + HW_DIM + row1], acc2[nt][3]);
            }
        }
    }
}

// ---------------------------------------------------------------- launcher
extern "C" void kernel_launch(void* const* d_in, const int* in_sizes, int n_in,
                              void* d_out, int out_size) {
    const float* x      = (const float*)d_in[0];
    const float* keys   = (const float*)d_in[1];
    const float* values = (const float*)d_in[2];
    float* out = (float*)d_out;

    cudaFuncSetAttribute(memmod_kernel,
                         cudaFuncAttributeMaxDynamicSharedMemorySize, SMEM_BYTES);

    prep_kernel<<<1, 256>>>(keys, values);
    dim3 grid(HW_DIM / (TILES_PER_CTA * TILE_PX), B_DIM);
    memmod_kernel<<<grid, 256, SMEM_BYTES>>>(x, out);
}